// round 2
// baseline (speedup 1.0000x reference)
#include <cuda_runtime.h>
#include <cstdint>
#include <cstddef>

#define DEVI __device__ __forceinline__

// ------------------------------------------------------------------
// Scratch (__device__ globals: allocation-free rule)
// ------------------------------------------------------------------
__device__ float g_scale[2][8192];                 // [branch-1][row]
__device__ float g_Q[3ull * 8 * 12 * 1024 * 64];   // [br][b][h][n][d]
__device__ float g_K[3ull * 8 * 12 * 1024 * 64];
__device__ float g_V[3ull * 8 * 12 * 1024 * 64];

// ------------------------------------------------------------------
// Helpers
// ------------------------------------------------------------------
DEVI void tf32_split(float v, uint32_t& hi, uint32_t& lo) {
    uint32_t h, l;
    asm("cvt.rna.tf32.f32 %0, %1;" : "=r"(h) : "f"(v));
    float r = v - __uint_as_float(h);
    asm("cvt.rna.tf32.f32 %0, %1;" : "=r"(l) : "f"(r));
    hi = h; lo = l;
}

DEVI void mma8(float d[4], const uint32_t a[4], const uint32_t b[2]) {
    asm volatile(
        "mma.sync.aligned.m16n8k8.row.col.f32.tf32.tf32.f32 "
        "{%0,%1,%2,%3}, {%4,%5,%6,%7}, {%8,%9}, {%0,%1,%2,%3};"
        : "+f"(d[0]), "+f"(d[1]), "+f"(d[2]), "+f"(d[3])
        : "r"(a[0]), "r"(a[1]), "r"(a[2]), "r"(a[3]), "r"(b[0]), "r"(b[1]));
}

// ------------------------------------------------------------------
// Kernel 1: per-row branch scalars.
// x_h = s_h * x (expmap0 + project), x_s = s_s * x (logmap0)
// ------------------------------------------------------------------
__global__ __launch_bounds__(256) void scales_kernel(const float* __restrict__ x) {
    __shared__ float red[8];
    const int row = blockIdx.x;
    const float* xr = x + (size_t)row * 768;
    float ss = 0.f;
    for (int i = threadIdx.x; i < 768; i += 256) { float v = xr[i]; ss = fmaf(v, v, ss); }
#pragma unroll
    for (int o = 16; o; o >>= 1) ss += __shfl_xor_sync(0xffffffffu, ss, o);
    if ((threadIdx.x & 31) == 0) red[threadIdx.x >> 5] = ss;
    __syncthreads();
    if (threadIdx.x == 0) {
        float t = 0.f;
#pragma unroll
        for (int i = 0; i < 8; ++i) t += red[i];
        float n = fmaxf(sqrtf(t), 1e-5f);
        const float sc = 0.316227766016837933f;     // sqrt(0.1)
        float a = sc * n;
        float th = tanhf(a);
        float s_pre = th / a;
        float norm_h = th / sc;                     // ||expmap0(x)||
        float maxn = (1.0f - 4e-3f) / sc;
        float s_h = (norm_h > maxn) ? s_pre * (maxn / norm_h) : s_pre;
        float arg = fminf(a, 1.0f - 1e-5f);
        float art = 0.5f * logf((1.0f + arg) / (1.0f - arg));
        float s_s = art / (n * sc);
        g_scale[0][row] = s_h;
        g_scale[1][row] = s_s;
    }
}

// ------------------------------------------------------------------
// Kernel 2: fused scaled projection GEMM, split-tf32.
// One CTA = 128x128 tile of one of 9 output matrices (br x {q,k,v}).
// out[r][c] = s_br(r) * (x[r,:] @ W[c,:]) + bias[c]
// ------------------------------------------------------------------
__global__ __launch_bounds__(256) void proj_kernel(
    const float* __restrict__ x,
    const float* __restrict__ wq, const float* __restrict__ bq,
    const float* __restrict__ wk, const float* __restrict__ bk,
    const float* __restrict__ wv, const float* __restrict__ bv)
{
    __shared__ float sA[128][36];
    __shared__ float sB[128][36];

    const int mat = blockIdx.z;                 // 0..8
    const int br  = mat % 3;
    const int typ = mat / 3;                    // 0=q 1=k 2=v
    const float* W  = (typ == 0 ? wq : typ == 1 ? wk : wv) + (size_t)br * 768 * 768;
    const float* Bb = (typ == 0 ? bq : typ == 1 ? bk : bv) + br * 768;
    float* dst = (typ == 0 ? g_Q : typ == 1 ? g_K : g_V);

    const int rt = blockIdx.x, ct = blockIdx.y;
    const int tid = threadIdx.x, lane = tid & 31, warp = tid >> 5;
    const int wr = warp >> 1, wc = warp & 1;    // 4x2 warp grid, warp tile 32x64

    float acc[2][8][4];
#pragma unroll
    for (int i = 0; i < 2; ++i)
#pragma unroll
        for (int j = 0; j < 8; ++j)
#pragma unroll
            for (int k = 0; k < 4; ++k) acc[i][j][k] = 0.f;

    // per-thread fill row / scale (constant over the k loop)
    int   fr[4];
    float fs[4];
    const float* fxp[4];
#pragma unroll
    for (int it = 0; it < 4; ++it) {
        int idx = it * 256 + tid;
        int r = idx >> 3;
        fr[it] = r;
        int grow = rt * 128 + r;
        fs[it] = (br == 0) ? 1.0f : g_scale[br - 1][grow];
        fxp[it] = x + (size_t)grow * 768;
    }

    for (int kt = 0; kt < 24; ++kt) {
#pragma unroll
        for (int it = 0; it < 4; ++it) {
            int idx = it * 256 + tid;
            int r = fr[it], c4 = (idx & 7) << 2;
            float4 va = *(const float4*)(fxp[it] + kt * 32 + c4);
            float s = fs[it];
            va.x *= s; va.y *= s; va.z *= s; va.w *= s;
            *(float4*)&sA[r][c4] = va;
            float4 vb = *(const float4*)&W[(size_t)(ct * 128 + r) * 768 + kt * 32 + c4];
            *(float4*)&sB[r][c4] = vb;
        }
        __syncthreads();
#pragma unroll
        for (int ks = 0; ks < 4; ++ks) {
            uint32_t ah[2][4], al[2][4];
#pragma unroll
            for (int mt = 0; mt < 2; ++mt) {
                int r0 = wr * 32 + mt * 16 + (lane >> 2);
                int c0 = ks * 8 + (lane & 3);
                tf32_split(sA[r0][c0],         ah[mt][0], al[mt][0]);
                tf32_split(sA[r0 + 8][c0],     ah[mt][1], al[mt][1]);
                tf32_split(sA[r0][c0 + 4],     ah[mt][2], al[mt][2]);
                tf32_split(sA[r0 + 8][c0 + 4], ah[mt][3], al[mt][3]);
            }
#pragma unroll
            for (int nt = 0; nt < 8; ++nt) {
                int n0 = wc * 64 + nt * 8 + (lane >> 2);
                int k0 = ks * 8 + (lane & 3);
                uint32_t bh[2], bl[2];
                tf32_split(sB[n0][k0],     bh[0], bl[0]);
                tf32_split(sB[n0][k0 + 4], bh[1], bl[1]);
#pragma unroll
                for (int mt = 0; mt < 2; ++mt) {
                    mma8(acc[mt][nt], ah[mt], bh);
                    mma8(acc[mt][nt], ah[mt], bl);
                    mma8(acc[mt][nt], al[mt], bh);
                }
            }
        }
        __syncthreads();
    }

    // epilogue: add bias, store into [br][b][h][n][64]
    const int h  = ct * 2 + wc;                 // 64-col block per warp-col
    const int bb = (rt * 128) >> 10;
    const int nb = (rt * 128) & 1023;
#pragma unroll
    for (int mt = 0; mt < 2; ++mt) {
        int r = wr * 32 + mt * 16 + (lane >> 2);
#pragma unroll
        for (int nt = 0; nt < 8; ++nt) {
            int d = nt * 8 + (lane & 3) * 2;
            float2 bi = *(const float2*)&Bb[h * 64 + d];
            size_t base = ((((size_t)br * 8 + bb) * 12 + h) * 1024 + (nb + r)) * 64 + d;
            *(float2*)&dst[base]          = make_float2(acc[mt][nt][0] + bi.x, acc[mt][nt][1] + bi.y);
            *(float2*)&dst[base + 8 * 64] = make_float2(acc[mt][nt][2] + bi.x, acc[mt][nt][3] + bi.y);
        }
    }
}

// ------------------------------------------------------------------
// Kernel 3: flash attention, branch loop inside CTA (no atomics).
// CTA = (qtile 128 rows, head, batch). 8 warps; warp owns 16 q-rows.
// NOTE: reference has NO 1/sqrt(dh) scaling.
// ------------------------------------------------------------------
__global__ __launch_bounds__(256) void attn_kernel(float* __restrict__ out) {
    extern __shared__ float smf[];
    float* sQ = smf;                    // [128][68]
    float* sK = smf + 128 * 68;         // [128][68]
    float* sV = smf + 2 * 128 * 68;     // [128][68] (kv-row major)
    float* sP = smf + 3 * 128 * 68;     // [128][132]

    const int qt = blockIdx.x, h = blockIdx.y, bb = blockIdx.z;
    const int tid = threadIdx.x, lane = tid & 31, warp = tid >> 5;
    const int g = lane >> 2, tg = lane & 3;
    const int r0 = warp * 16 + g;       // this thread's first q-row (local)

    float of[8][4];
#pragma unroll
    for (int i = 0; i < 8; ++i)
#pragma unroll
        for (int j = 0; j < 4; ++j) of[i][j] = 0.f;

    for (int brn = 0; brn < 3; ++brn) {
        const size_t hb = (((size_t)brn * 8 + bb) * 12 + h) * (size_t)(1024 * 64);
        __syncthreads();                // protect sQ from previous branch's reads
#pragma unroll
        for (int it = 0; it < 8; ++it) {
            int idx = it * 256 + tid;
            int r = idx >> 4, c4 = (idx & 15) << 2;
            *(float4*)&sQ[r * 68 + c4] =
                *(const float4*)&g_Q[hb + (size_t)(qt * 128 + r) * 64 + c4];
        }

        float m0 = -1e30f, m1 = -1e30f, l0 = 0.f, l1 = 0.f;
        float oa[8][4];
#pragma unroll
        for (int i = 0; i < 8; ++i)
#pragma unroll
            for (int j = 0; j < 4; ++j) oa[i][j] = 0.f;

        for (int jt = 0; jt < 8; ++jt) {
            __syncthreads();            // prev tile's mma done reading sK/sV; sQ visible
#pragma unroll
            for (int it = 0; it < 8; ++it) {
                int idx = it * 256 + tid;
                int r = idx >> 4, c4 = (idx & 15) << 2;
                size_t go = hb + (size_t)(jt * 128 + r) * 64 + c4;
                *(float4*)&sK[r * 68 + c4] = *(const float4*)&g_K[go];
                *(float4*)&sV[r * 68 + c4] = *(const float4*)&g_V[go];
            }
            __syncthreads();

            // ---- S = Q K^T (16 q-rows x 128 kv-cols per warp), split-tf32 ----
            float sf[16][4];
#pragma unroll
            for (int i = 0; i < 16; ++i)
#pragma unroll
                for (int j = 0; j < 4; ++j) sf[i][j] = 0.f;
#pragma unroll
            for (int ks = 0; ks < 8; ++ks) {
                int c0 = ks * 8 + tg;
                uint32_t ah[4], al[4];
                tf32_split(sQ[r0 * 68 + c0],           ah[0], al[0]);
                tf32_split(sQ[(r0 + 8) * 68 + c0],     ah[1], al[1]);
                tf32_split(sQ[r0 * 68 + c0 + 4],       ah[2], al[2]);
                tf32_split(sQ[(r0 + 8) * 68 + c0 + 4], ah[3], al[3]);
#pragma unroll
                for (int nt = 0; nt < 16; ++nt) {
                    int n0 = nt * 8 + g;
                    uint32_t bh[2], bl[2];
                    tf32_split(sK[n0 * 68 + c0],     bh[0], bl[0]);
                    tf32_split(sK[n0 * 68 + c0 + 4], bh[1], bl[1]);
                    mma8(sf[nt], ah, bh);
                    mma8(sf[nt], ah, bl);
                    mma8(sf[nt], al, bh);
                }
            }

            // ---- online softmax (rows fully within warp; reduce over 4 lanes) ----
            float t0 = -1e30f, t1 = -1e30f;
#pragma unroll
            for (int nt = 0; nt < 16; ++nt) {
                t0 = fmaxf(t0, fmaxf(sf[nt][0], sf[nt][1]));
                t1 = fmaxf(t1, fmaxf(sf[nt][2], sf[nt][3]));
            }
            t0 = fmaxf(t0, __shfl_xor_sync(0xffffffffu, t0, 1));
            t0 = fmaxf(t0, __shfl_xor_sync(0xffffffffu, t0, 2));
            t1 = fmaxf(t1, __shfl_xor_sync(0xffffffffu, t1, 1));
            t1 = fmaxf(t1, __shfl_xor_sync(0xffffffffu, t1, 2));
            float mn0 = fmaxf(m0, t0), mn1 = fmaxf(m1, t1);
            float a0 = __expf(m0 - mn0), a1 = __expf(m1 - mn1);
            m0 = mn0; m1 = mn1;

            float rs0 = 0.f, rs1 = 0.f;
#pragma unroll
            for (int nt = 0; nt < 16; ++nt) {
                sf[nt][0] = __expf(sf[nt][0] - mn0);
                sf[nt][1] = __expf(sf[nt][1] - mn0);
                sf[nt][2] = __expf(sf[nt][2] - mn1);
                sf[nt][3] = __expf(sf[nt][3] - mn1);
                rs0 += sf[nt][0] + sf[nt][1];
                rs1 += sf[nt][2] + sf[nt][3];
            }
            l0 = l0 * a0 + rs0;
            l1 = l1 * a1 + rs1;
#pragma unroll
            for (int nt = 0; nt < 8; ++nt) {
                oa[nt][0] *= a0; oa[nt][1] *= a0;
                oa[nt][2] *= a1; oa[nt][3] *= a1;
            }

            // ---- P -> warp-private smem strip, then O += P V (split-tf32) ----
#pragma unroll
            for (int nt = 0; nt < 16; ++nt) {
                int c = nt * 8 + tg * 2;
                sP[r0 * 132 + c]           = sf[nt][0];
                sP[r0 * 132 + c + 1]       = sf[nt][1];
                sP[(r0 + 8) * 132 + c]     = sf[nt][2];
                sP[(r0 + 8) * 132 + c + 1] = sf[nt][3];
            }
            __syncwarp();
#pragma unroll
            for (int ks = 0; ks < 16; ++ks) {
                int c0 = ks * 8 + tg;
                uint32_t ah[4], al[4];
                tf32_split(sP[r0 * 132 + c0],           ah[0], al[0]);
                tf32_split(sP[(r0 + 8) * 132 + c0],     ah[1], al[1]);
                tf32_split(sP[r0 * 132 + c0 + 4],       ah[2], al[2]);
                tf32_split(sP[(r0 + 8) * 132 + c0 + 4], ah[3], al[3]);
#pragma unroll
                for (int nt = 0; nt < 8; ++nt) {
                    int n0 = nt * 8 + g;
                    uint32_t bh[2], bl[2];
                    tf32_split(sV[c0 * 68 + n0],       bh[0], bl[0]);
                    tf32_split(sV[(c0 + 4) * 68 + n0], bh[1], bl[1]);
                    mma8(oa[nt], ah, bh);
                    mma8(oa[nt], ah, bl);
                    mma8(oa[nt], al, bh);
                }
            }
        }

        // fold branch into final accumulator (normalize by row sum)
        float L0 = l0 + __shfl_xor_sync(0xffffffffu, l0, 1);
        L0 += __shfl_xor_sync(0xffffffffu, L0, 2);
        float L1 = l1 + __shfl_xor_sync(0xffffffffu, l1, 1);
        L1 += __shfl_xor_sync(0xffffffffu, L1, 2);
        float i0 = 1.f / L0, i1 = 1.f / L1;
#pragma unroll
        for (int nt = 0; nt < 8; ++nt) {
            of[nt][0] += oa[nt][0] * i0;
            of[nt][1] += oa[nt][1] * i0;
            of[nt][2] += oa[nt][2] * i1;
            of[nt][3] += oa[nt][3] * i1;
        }
    }

    // write out[b][n][h*64+d]
#pragma unroll
    for (int nt = 0; nt < 8; ++nt) {
        int d = nt * 8 + tg * 2;
        size_t base = ((size_t)bb * 1024 + (size_t)(qt * 128 + r0)) * 768 + h * 64 + d;
        *(float2*)&out[base]                   = make_float2(of[nt][0], of[nt][1]);
        *(float2*)&out[base + (size_t)8 * 768] = make_float2(of[nt][2], of[nt][3]);
    }
}

// ------------------------------------------------------------------
extern "C" void kernel_launch(void* const* d_in, const int* in_sizes, int n_in,
                              void* d_out, int out_size) {
    (void)in_sizes; (void)n_in; (void)out_size;
    const float* x  = (const float*)d_in[0];
    const float* wq = (const float*)d_in[1];
    const float* bq = (const float*)d_in[2];
    const float* wk = (const float*)d_in[3];
    const float* bk = (const float*)d_in[4];
    const float* wv = (const float*)d_in[5];
    const float* bv = (const float*)d_in[6];
    float* out = (float*)d_out;

    scales_kernel<<<8192, 256>>>(x);
    proj_kernel<<<dim3(64, 6, 9), 256>>>(x, wq, bq, wk, bk, wv, bv);

    const int smem_bytes = 128 * 336 * 4;   // 172032 B
    cudaFuncSetAttribute(attn_kernel, cudaFuncAttributeMaxDynamicSharedMemorySize, smem_bytes);
    attn_kernel<<<dim3(8, 12, 8), 256, smem_bytes>>>(out);
}

// round 3
// speedup vs baseline: 1.7971x; 1.7971x over previous
#include <cuda_runtime.h>
#include <cuda_bf16.h>
#include <cstdint>
#include <cstddef>

#define DEVI __device__ __forceinline__

// ------------------------------------------------------------------
// Scratch: pre-split bf16 planes (hi + mid) for Q,K,V  [br][b][h][n][64]
// ------------------------------------------------------------------
__device__ float g_scale[2][8192];
__device__ __nv_bfloat16 g_Qh[3ull * 8 * 12 * 1024 * 64];
__device__ __nv_bfloat16 g_Qm[3ull * 8 * 12 * 1024 * 64];
__device__ __nv_bfloat16 g_Kh[3ull * 8 * 12 * 1024 * 64];
__device__ __nv_bfloat16 g_Km[3ull * 8 * 12 * 1024 * 64];
__device__ __nv_bfloat16 g_Vh[3ull * 8 * 12 * 1024 * 64];
__device__ __nv_bfloat16 g_Vm[3ull * 8 * 12 * 1024 * 64];

// ------------------------------------------------------------------
// Helpers
// ------------------------------------------------------------------
DEVI uint32_t smaddr(const void* p) { return (uint32_t)__cvta_generic_to_shared(p); }

DEVI void ldsm4(uint32_t r[4], uint32_t a) {
    asm volatile("ldmatrix.sync.aligned.m8n8.x4.shared.b16 {%0,%1,%2,%3}, [%4];"
                 : "=r"(r[0]), "=r"(r[1]), "=r"(r[2]), "=r"(r[3]) : "r"(a));
}
DEVI void ldsm4t(uint32_t r[4], uint32_t a) {
    asm volatile("ldmatrix.sync.aligned.m8n8.x4.trans.shared.b16 {%0,%1,%2,%3}, [%4];"
                 : "=r"(r[0]), "=r"(r[1]), "=r"(r[2]), "=r"(r[3]) : "r"(a));
}

DEVI void mma16(float d[4], const uint32_t a[4], const uint32_t b[2]) {
    asm volatile(
        "mma.sync.aligned.m16n8k16.row.col.f32.bf16.bf16.f32 "
        "{%0,%1,%2,%3}, {%4,%5,%6,%7}, {%8,%9}, {%0,%1,%2,%3};"
        : "+f"(d[0]), "+f"(d[1]), "+f"(d[2]), "+f"(d[3])
        : "r"(a[0]), "r"(a[1]), "r"(a[2]), "r"(a[3]), "r"(b[0]), "r"(b[1]));
}

DEVI uint32_t packh(float a, float b) {
    __nv_bfloat16 ha = __float2bfloat16(a), hb = __float2bfloat16(b);
    uint16_t ua, ub;
    memcpy(&ua, &ha, 2); memcpy(&ub, &hb, 2);
    return ((uint32_t)ub << 16) | ua;
}
DEVI uint32_t packm(float a, float b, uint32_t h) {
    uint16_t ua = (uint16_t)(h & 0xffffu), ub = (uint16_t)(h >> 16);
    __nv_bfloat16 ha, hb;
    memcpy(&ha, &ua, 2); memcpy(&hb, &ub, 2);
    return packh(a - __bfloat162float(ha), b - __bfloat162float(hb));
}

// ------------------------------------------------------------------
// Kernel 1: per-row branch scalars (all 3 geometric maps are s(|x|)*x)
// ------------------------------------------------------------------
__global__ __launch_bounds__(256) void scales_kernel(const float* __restrict__ x) {
    __shared__ float red[8];
    const int row = blockIdx.x;
    const float* xr = x + (size_t)row * 768;
    float ss = 0.f;
    for (int i = threadIdx.x; i < 768; i += 256) { float v = xr[i]; ss = fmaf(v, v, ss); }
#pragma unroll
    for (int o = 16; o; o >>= 1) ss += __shfl_xor_sync(0xffffffffu, ss, o);
    if ((threadIdx.x & 31) == 0) red[threadIdx.x >> 5] = ss;
    __syncthreads();
    if (threadIdx.x == 0) {
        float t = 0.f;
#pragma unroll
        for (int i = 0; i < 8; ++i) t += red[i];
        float n = fmaxf(sqrtf(t), 1e-5f);
        const float sc = 0.316227766016837933f;     // sqrt(0.1)
        float a = sc * n;
        float th = tanhf(a);
        float s_pre = th / a;
        float norm_h = th / sc;
        float maxn = (1.0f - 4e-3f) / sc;
        float s_h = (norm_h > maxn) ? s_pre * (maxn / norm_h) : s_pre;
        float arg = fminf(a, 1.0f - 1e-5f);
        float art = 0.5f * logf((1.0f + arg) / (1.0f - arg));
        float s_s = art / (n * sc);
        g_scale[0][row] = s_h;
        g_scale[1][row] = s_s;
    }
}

// ------------------------------------------------------------------
// Kernel 2: scaled projection GEMM, bf16 3-pass (hh+hm+mh), ldmatrix.
// CTA = 128x128 tile; epilogue writes hi/mid bf16 planes head-major.
// ------------------------------------------------------------------
__global__ __launch_bounds__(256) void proj_kernel(
    const float* __restrict__ x,
    const float* __restrict__ wq, const float* __restrict__ bq,
    const float* __restrict__ wk, const float* __restrict__ bk,
    const float* __restrict__ wv, const float* __restrict__ bv)
{
    __shared__ __nv_bfloat16 sAh[128][40];   // 80B row stride: 16B-aligned, 5r mod 8 distinct
    __shared__ __nv_bfloat16 sAm[128][40];
    __shared__ __nv_bfloat16 sBh[128][40];
    __shared__ __nv_bfloat16 sBm[128][40];

    const int mat = blockIdx.z;
    const int br  = mat % 3;
    const int typ = mat / 3;                 // 0=q 1=k 2=v
    const float* W  = (typ == 0 ? wq : typ == 1 ? wk : wv) + (size_t)br * 768 * 768;
    const float* Bb = (typ == 0 ? bq : typ == 1 ? bk : bv) + br * 768;
    __nv_bfloat16* dh = (typ == 0 ? g_Qh : typ == 1 ? g_Kh : g_Vh);
    __nv_bfloat16* dm = (typ == 0 ? g_Qm : typ == 1 ? g_Km : g_Vm);

    const int rt = blockIdx.x, ct = blockIdx.y;
    const int tid = threadIdx.x, lane = tid & 31, warp = tid >> 5;
    const int wr = warp >> 1, wc = warp & 1;         // warp tile 32x64
    const int l7 = lane & 7, l8 = lane & 8, l16 = (lane & 16) >> 1;

    float acc[2][8][4];
#pragma unroll
    for (int i = 0; i < 2; ++i)
#pragma unroll
        for (int j = 0; j < 8; ++j)
#pragma unroll
            for (int k = 0; k < 4; ++k) acc[i][j][k] = 0.f;

    int   fr[4];
    float fs[4];
    const float* fxp[4];
#pragma unroll
    for (int it = 0; it < 4; ++it) {
        int idx = it * 256 + tid;
        int r = idx >> 3;
        fr[it] = r;
        int grow = rt * 128 + r;
        fs[it] = (br == 0) ? 1.0f : g_scale[br - 1][grow];
        fxp[it] = x + (size_t)grow * 768;
    }

    for (int kt = 0; kt < 24; ++kt) {
#pragma unroll
        for (int it = 0; it < 4; ++it) {
            int idx = it * 256 + tid;
            int r = fr[it], c4 = (idx & 7) << 2;
            float4 va = *(const float4*)(fxp[it] + kt * 32 + c4);
            float s = fs[it];
            va.x *= s; va.y *= s; va.z *= s; va.w *= s;
            uint32_t h0 = packh(va.x, va.y), h1 = packh(va.z, va.w);
            *(uint32_t*)&sAh[r][c4]     = h0;
            *(uint32_t*)&sAh[r][c4 + 2] = h1;
            *(uint32_t*)&sAm[r][c4]     = packm(va.x, va.y, h0);
            *(uint32_t*)&sAm[r][c4 + 2] = packm(va.z, va.w, h1);
            float4 vb = *(const float4*)&W[(size_t)(ct * 128 + r) * 768 + kt * 32 + c4];
            uint32_t g0 = packh(vb.x, vb.y), g1 = packh(vb.z, vb.w);
            *(uint32_t*)&sBh[r][c4]     = g0;
            *(uint32_t*)&sBh[r][c4 + 2] = g1;
            *(uint32_t*)&sBm[r][c4]     = packm(vb.x, vb.y, g0);
            *(uint32_t*)&sBm[r][c4 + 2] = packm(vb.z, vb.w, g1);
        }
        __syncthreads();
#pragma unroll
        for (int ks = 0; ks < 2; ++ks) {
            const int k0 = ks * 16;
            uint32_t ah[2][4], am_[2][4];
#pragma unroll
            for (int mt = 0; mt < 2; ++mt) {
                int r0 = wr * 32 + mt * 16 + l7 + l8;
                ldsm4(ah[mt],  smaddr(&sAh[r0][k0 + l16]));
                ldsm4(am_[mt], smaddr(&sAm[r0][k0 + l16]));
            }
#pragma unroll
            for (int p = 0; p < 4; ++p) {
                int n0 = wc * 64 + p * 16 + l7 + l16;
                uint32_t bh[4], bm_[4];
                ldsm4(bh,  smaddr(&sBh[n0][k0 + l8]));
                ldsm4(bm_, smaddr(&sBm[n0][k0 + l8]));
#pragma unroll
                for (int mt = 0; mt < 2; ++mt) {
                    mma16(acc[mt][2 * p],     ah[mt],  bh);
                    mma16(acc[mt][2 * p],     ah[mt],  bm_);
                    mma16(acc[mt][2 * p],     am_[mt], bh);
                    mma16(acc[mt][2 * p + 1], ah[mt],  bh + 2);
                    mma16(acc[mt][2 * p + 1], ah[mt],  bm_ + 2);
                    mma16(acc[mt][2 * p + 1], am_[mt], bh + 2);
                }
            }
        }
        __syncthreads();
    }

    // epilogue: bias, split to bf16 hi/mid planes [br][b][h][n][64]
    const int h  = ct * 2 + wc;
    const int bb = (rt * 128) >> 10;
    const int nb = (rt * 128) & 1023;
    const int tg = lane & 3, g = lane >> 2;
#pragma unroll
    for (int mt = 0; mt < 2; ++mt) {
        int r = wr * 32 + mt * 16 + g;
#pragma unroll
        for (int nt = 0; nt < 8; ++nt) {
            int d = nt * 8 + tg * 2;
            float2 bi = *(const float2*)&Bb[h * 64 + d];
            float v0 = acc[mt][nt][0] + bi.x, v1 = acc[mt][nt][1] + bi.y;
            float v2 = acc[mt][nt][2] + bi.x, v3 = acc[mt][nt][3] + bi.y;
            size_t base = ((((size_t)br * 8 + bb) * 12 + h) * 1024 + (nb + r)) * 64 + d;
            uint32_t h0 = packh(v0, v1), h1 = packh(v2, v3);
            *(uint32_t*)&dh[base]          = h0;
            *(uint32_t*)&dh[base + 8 * 64] = h1;
            *(uint32_t*)&dm[base]          = packm(v0, v1, h0);
            *(uint32_t*)&dm[base + 8 * 64] = packm(v2, v3, h1);
        }
    }
}

// ------------------------------------------------------------------
// Kernel 3: flash attention, bf16 3-pass. P stays in registers
// (S C-fragment == PV A-fragment). V loaded via ldmatrix.trans.
// Branch sum via gmem RMW (CTA owns its out tile for all 3 branches).
// ------------------------------------------------------------------
__global__ __launch_bounds__(256) void attn_kernel(float* __restrict__ out) {
    extern __shared__ __nv_bfloat16 smb[];
    __nv_bfloat16 (*sQh)[72] = (__nv_bfloat16(*)[72])(smb);
    __nv_bfloat16 (*sQm)[72] = (__nv_bfloat16(*)[72])(smb + 128 * 72);
    __nv_bfloat16 (*sKh)[72] = (__nv_bfloat16(*)[72])(smb + 2 * 128 * 72);
    __nv_bfloat16 (*sKm)[72] = (__nv_bfloat16(*)[72])(smb + 3 * 128 * 72);
    __nv_bfloat16 (*sVh)[72] = (__nv_bfloat16(*)[72])(smb + 4 * 128 * 72);
    __nv_bfloat16 (*sVm)[72] = (__nv_bfloat16(*)[72])(smb + 5 * 128 * 72);

    const int qt = blockIdx.x, h = blockIdx.y, bb = blockIdx.z;
    const int tid = threadIdx.x, lane = tid & 31, warp = tid >> 5;
    const int g = lane >> 2, tg = lane & 3;
    const int l7 = lane & 7, l8 = lane & 8, l16 = (lane & 16) >> 1;
    const int r0 = warp * 16 + g;

    for (int brn = 0; brn < 3; ++brn) {
        const size_t hb = (((size_t)brn * 8 + bb) * 12 + h) * (size_t)(1024 * 64);
        __syncthreads();
#pragma unroll
        for (int it = 0; it < 16; ++it) {
            int idx = it * 256 + tid;
            int r = idx >> 5, c = (idx & 31) * 2;
            size_t go = hb + (size_t)(qt * 128 + r) * 64 + c;
            *(uint32_t*)&sQh[r][c] = *(const uint32_t*)&g_Qh[go];
            *(uint32_t*)&sQm[r][c] = *(const uint32_t*)&g_Qm[go];
        }

        float m0 = -1e30f, m1 = -1e30f, l0 = 0.f, l1 = 0.f;
        float oa[8][4];
#pragma unroll
        for (int i = 0; i < 8; ++i)
#pragma unroll
            for (int j = 0; j < 4; ++j) oa[i][j] = 0.f;

        for (int jt = 0; jt < 8; ++jt) {
            __syncthreads();
#pragma unroll
            for (int it = 0; it < 16; ++it) {
                int idx = it * 256 + tid;
                int r = idx >> 5, c = (idx & 31) * 2;
                size_t go = hb + (size_t)(jt * 128 + r) * 64 + c;
                *(uint32_t*)&sKh[r][c] = *(const uint32_t*)&g_Kh[go];
                *(uint32_t*)&sKm[r][c] = *(const uint32_t*)&g_Km[go];
                *(uint32_t*)&sVh[r][c] = *(const uint32_t*)&g_Vh[go];
                *(uint32_t*)&sVm[r][c] = *(const uint32_t*)&g_Vm[go];
            }
            __syncthreads();

            // ---- S = Q K^T : 16 rows x 128 cols per warp ----
            float sf[16][4];
#pragma unroll
            for (int i = 0; i < 16; ++i)
#pragma unroll
                for (int j = 0; j < 4; ++j) sf[i][j] = 0.f;
#pragma unroll
            for (int ks = 0; ks < 4; ++ks) {
                const int k0 = ks * 16;
                uint32_t qh[4], qm[4];
                ldsm4(qh, smaddr(&sQh[warp * 16 + l7 + l8][k0 + l16]));
                ldsm4(qm, smaddr(&sQm[warp * 16 + l7 + l8][k0 + l16]));
#pragma unroll
                for (int p = 0; p < 8; ++p) {
                    int n0 = p * 16 + l7 + l16;
                    uint32_t kh_[4], km_[4];
                    ldsm4(kh_, smaddr(&sKh[n0][k0 + l8]));
                    ldsm4(km_, smaddr(&sKm[n0][k0 + l8]));
                    mma16(sf[2 * p],     qh, kh_);
                    mma16(sf[2 * p],     qh, km_);
                    mma16(sf[2 * p],     qm, kh_);
                    mma16(sf[2 * p + 1], qh, kh_ + 2);
                    mma16(sf[2 * p + 1], qh, km_ + 2);
                    mma16(sf[2 * p + 1], qm, kh_ + 2);
                }
            }

            // ---- online softmax ----
            float t0 = -1e30f, t1 = -1e30f;
#pragma unroll
            for (int nt = 0; nt < 16; ++nt) {
                t0 = fmaxf(t0, fmaxf(sf[nt][0], sf[nt][1]));
                t1 = fmaxf(t1, fmaxf(sf[nt][2], sf[nt][3]));
            }
            t0 = fmaxf(t0, __shfl_xor_sync(0xffffffffu, t0, 1));
            t0 = fmaxf(t0, __shfl_xor_sync(0xffffffffu, t0, 2));
            t1 = fmaxf(t1, __shfl_xor_sync(0xffffffffu, t1, 1));
            t1 = fmaxf(t1, __shfl_xor_sync(0xffffffffu, t1, 2));
            float mn0 = fmaxf(m0, t0), mn1 = fmaxf(m1, t1);
            float a0 = __expf(m0 - mn0), a1 = __expf(m1 - mn1);
            m0 = mn0; m1 = mn1;

            float rs0 = 0.f, rs1 = 0.f;
#pragma unroll
            for (int nt = 0; nt < 16; ++nt) {
                sf[nt][0] = __expf(sf[nt][0] - mn0);
                sf[nt][1] = __expf(sf[nt][1] - mn0);
                sf[nt][2] = __expf(sf[nt][2] - mn1);
                sf[nt][3] = __expf(sf[nt][3] - mn1);
                rs0 += sf[nt][0] + sf[nt][1];
                rs1 += sf[nt][2] + sf[nt][3];
            }
            l0 = l0 * a0 + rs0;
            l1 = l1 * a1 + rs1;
#pragma unroll
            for (int nt = 0; nt < 8; ++nt) {
                oa[nt][0] *= a0; oa[nt][1] *= a0;
                oa[nt][2] *= a1; oa[nt][3] *= a1;
            }

            // ---- O += P V : P fragments built in registers from sf ----
#pragma unroll
            for (int ks = 0; ks < 8; ++ks) {
                uint32_t ph[4], pm[4];
                ph[0] = packh(sf[2 * ks][0],     sf[2 * ks][1]);
                ph[1] = packh(sf[2 * ks][2],     sf[2 * ks][3]);
                ph[2] = packh(sf[2 * ks + 1][0], sf[2 * ks + 1][1]);
                ph[3] = packh(sf[2 * ks + 1][2], sf[2 * ks + 1][3]);
                pm[0] = packm(sf[2 * ks][0],     sf[2 * ks][1],     ph[0]);
                pm[1] = packm(sf[2 * ks][2],     sf[2 * ks][3],     ph[1]);
                pm[2] = packm(sf[2 * ks + 1][0], sf[2 * ks + 1][1], ph[2]);
                pm[3] = packm(sf[2 * ks + 1][2], sf[2 * ks + 1][3], ph[3]);
                const int kv0 = ks * 16 + l7 + l8;
#pragma unroll
                for (int p = 0; p < 4; ++p) {
                    int d0 = p * 16 + l16;
                    uint32_t vh_[4], vm_[4];
                    ldsm4t(vh_, smaddr(&sVh[kv0][d0]));
                    ldsm4t(vm_, smaddr(&sVm[kv0][d0]));
                    mma16(oa[2 * p],     ph, vh_);
                    mma16(oa[2 * p],     ph, vm_);
                    mma16(oa[2 * p],     pm, vh_);
                    mma16(oa[2 * p + 1], ph, vh_ + 2);
                    mma16(oa[2 * p + 1], ph, vm_ + 2);
                    mma16(oa[2 * p + 1], pm, vh_ + 2);
                }
            }
        }

        // fold branch into out (RMW; CTA owns this tile across branches)
        float L0 = l0 + __shfl_xor_sync(0xffffffffu, l0, 1);
        L0 += __shfl_xor_sync(0xffffffffu, L0, 2);
        float L1 = l1 + __shfl_xor_sync(0xffffffffu, l1, 1);
        L1 += __shfl_xor_sync(0xffffffffu, L1, 2);
        float i0 = 1.f / L0, i1 = 1.f / L1;
#pragma unroll
        for (int nt = 0; nt < 8; ++nt) {
            int d = nt * 8 + tg * 2;
            size_t base = ((size_t)bb * 1024 + (size_t)(qt * 128 + r0)) * 768 + h * 64 + d;
            float2 v0 = make_float2(oa[nt][0] * i0, oa[nt][1] * i0);
            float2 v1 = make_float2(oa[nt][2] * i1, oa[nt][3] * i1);
            if (brn) {
                float2 o0 = *(float2*)&out[base];
                float2 o1 = *(float2*)&out[base + (size_t)8 * 768];
                v0.x += o0.x; v0.y += o0.y; v1.x += o1.x; v1.y += o1.y;
            }
            *(float2*)&out[base]                   = v0;
            *(float2*)&out[base + (size_t)8 * 768] = v1;
        }
    }
}

// ------------------------------------------------------------------
extern "C" void kernel_launch(void* const* d_in, const int* in_sizes, int n_in,
                              void* d_out, int out_size) {
    (void)in_sizes; (void)n_in; (void)out_size;
    const float* x  = (const float*)d_in[0];
    const float* wq = (const float*)d_in[1];
    const float* bq = (const float*)d_in[2];
    const float* wk = (const float*)d_in[3];
    const float* bk = (const float*)d_in[4];
    const float* wv = (const float*)d_in[5];
    const float* bv = (const float*)d_in[6];
    float* out = (float*)d_out;

    scales_kernel<<<8192, 256>>>(x);
    proj_kernel<<<dim3(64, 6, 9), 256>>>(x, wq, bq, wk, bk, wv, bv);

    const int smem_bytes = 6 * 128 * 72 * 2;   // 110592 B
    cudaFuncSetAttribute(attn_kernel, cudaFuncAttributeMaxDynamicSharedMemorySize, smem_bytes);
    attn_kernel<<<dim3(8, 12, 8), 256, smem_bytes>>>(out);
}

// round 5
// speedup vs baseline: 2.5158x; 1.4000x over previous
#include <cuda_runtime.h>
#include <cuda_bf16.h>
#include <cstdint>
#include <cstddef>

#define DEVI __device__ __forceinline__

// ------------------------------------------------------------------
// Scratch (__device__ globals; allocation-free rule)
// ------------------------------------------------------------------
__device__ float g_scale[2][8192];
// pre-split planes of branch-scaled x and of the 9 weight matrices
__device__ __nv_bfloat16 g_xh[3ull * 8192 * 768];
__device__ __nv_bfloat16 g_xm[3ull * 8192 * 768];
__device__ __nv_bfloat16 g_Wh[9ull * 768 * 768];
__device__ __nv_bfloat16 g_Wm[9ull * 768 * 768];
// pre-split Q/K/V planes [br][b][h][n][64]
__device__ __nv_bfloat16 g_Qh[3ull * 8 * 12 * 1024 * 64];
__device__ __nv_bfloat16 g_Qm[3ull * 8 * 12 * 1024 * 64];
__device__ __nv_bfloat16 g_Kh[3ull * 8 * 12 * 1024 * 64];
__device__ __nv_bfloat16 g_Km[3ull * 8 * 12 * 1024 * 64];
__device__ __nv_bfloat16 g_Vh[3ull * 8 * 12 * 1024 * 64];
__device__ __nv_bfloat16 g_Vm[3ull * 8 * 12 * 1024 * 64];

// ------------------------------------------------------------------
// Helpers
// ------------------------------------------------------------------
DEVI uint32_t smaddr(const void* p) { return (uint32_t)__cvta_generic_to_shared(p); }

DEVI uint32_t packh(float a, float b) {
    __nv_bfloat16 ha = __float2bfloat16(a), hb = __float2bfloat16(b);
    uint16_t ua, ub;
    memcpy(&ua, &ha, 2); memcpy(&ub, &hb, 2);
    return ((uint32_t)ub << 16) | ua;
}
DEVI uint32_t packm(float a, float b, uint32_t h) {
    uint16_t ua = (uint16_t)(h & 0xffffu), ub = (uint16_t)(h >> 16);
    __nv_bfloat16 ha, hb;
    memcpy(&ha, &ua, 2); memcpy(&hb, &ub, 2);
    return packh(a - __bfloat162float(ha), b - __bfloat162float(hb));
}

DEVI void cp16(uint32_t dst, const void* src) {
    asm volatile("cp.async.cg.shared.global [%0], [%1], 16;" :: "r"(dst), "l"(src) : "memory");
}
DEVI void cp_commit() { asm volatile("cp.async.commit_group;" ::: "memory"); }
DEVI void cp_wait0()  { asm volatile("cp.async.wait_group 0;" ::: "memory"); }
DEVI void cp_wait1()  { asm volatile("cp.async.wait_group 1;" ::: "memory"); }

DEVI void ldsm4(uint32_t r[4], uint32_t a) {
    asm volatile("ldmatrix.sync.aligned.m8n8.x4.shared.b16 {%0,%1,%2,%3}, [%4];"
                 : "=r"(r[0]), "=r"(r[1]), "=r"(r[2]), "=r"(r[3]) : "r"(a));
}
DEVI void ldsm4t(uint32_t r[4], uint32_t a) {
    asm volatile("ldmatrix.sync.aligned.m8n8.x4.trans.shared.b16 {%0,%1,%2,%3}, [%4];"
                 : "=r"(r[0]), "=r"(r[1]), "=r"(r[2]), "=r"(r[3]) : "r"(a));
}
DEVI void mma16(float d[4], const uint32_t a[4], const uint32_t b[2]) {
    asm volatile(
        "mma.sync.aligned.m16n8k16.row.col.f32.bf16.bf16.f32 "
        "{%0,%1,%2,%3}, {%4,%5,%6,%7}, {%8,%9}, {%0,%1,%2,%3};"
        : "+f"(d[0]), "+f"(d[1]), "+f"(d[2]), "+f"(d[3])
        : "r"(a[0]), "r"(a[1]), "r"(a[2]), "r"(a[3]), "r"(b[0]), "r"(b[1]));
}

// ------------------------------------------------------------------
// Kernel 1: per-row branch scalars (all 3 geometric maps are s(|x|)*x)
// ------------------------------------------------------------------
__global__ __launch_bounds__(256) void scales_kernel(const float* __restrict__ x) {
    __shared__ float red[8];
    const int row = blockIdx.x;
    const float* xr = x + (size_t)row * 768;
    float ss = 0.f;
    for (int i = threadIdx.x; i < 768; i += 256) { float v = xr[i]; ss = fmaf(v, v, ss); }
#pragma unroll
    for (int o = 16; o; o >>= 1) ss += __shfl_xor_sync(0xffffffffu, ss, o);
    if ((threadIdx.x & 31) == 0) red[threadIdx.x >> 5] = ss;
    __syncthreads();
    if (threadIdx.x == 0) {
        float t = 0.f;
#pragma unroll
        for (int i = 0; i < 8; ++i) t += red[i];
        float n = fmaxf(sqrtf(t), 1e-5f);
        const float sc = 0.316227766016837933f;     // sqrt(0.1)
        float a = sc * n;
        float th = tanhf(a);
        float s_pre = th / a;
        float norm_h = th / sc;
        float maxn = (1.0f - 4e-3f) / sc;
        float s_h = (norm_h > maxn) ? s_pre * (maxn / norm_h) : s_pre;
        float arg = fminf(a, 1.0f - 1e-5f);
        float art = 0.5f * logf((1.0f + arg) / (1.0f - arg));
        float s_s = art / (n * sc);
        g_scale[0][row] = s_h;
        g_scale[1][row] = s_s;
    }
}

// ------------------------------------------------------------------
// Kernel 1b/1c: pre-split branch-scaled x and weights into bf16 planes
// ------------------------------------------------------------------
__global__ __launch_bounds__(192) void prep_x(const float* __restrict__ x) {
    const int row = blockIdx.x, br = blockIdx.y;
    const float s = (br == 0) ? 1.0f : g_scale[br - 1][row];
    const int c = threadIdx.x * 4;
    float4 v = *(const float4*)&x[(size_t)row * 768 + c];
    v.x *= s; v.y *= s; v.z *= s; v.w *= s;
    size_t o = ((size_t)br * 8192 + row) * 768 + c;
    uint32_t h0 = packh(v.x, v.y), h1 = packh(v.z, v.w);
    *(uint32_t*)&g_xh[o]     = h0;
    *(uint32_t*)&g_xh[o + 2] = h1;
    *(uint32_t*)&g_xm[o]     = packm(v.x, v.y, h0);
    *(uint32_t*)&g_xm[o + 2] = packm(v.z, v.w, h1);
}

__global__ __launch_bounds__(192) void prep_w(
    const float* __restrict__ wq, const float* __restrict__ wk, const float* __restrict__ wv) {
    const int row = blockIdx.x, mat = blockIdx.y;
    const int typ = mat / 3, br = mat % 3;
    const float* W = (typ == 0 ? wq : typ == 1 ? wk : wv) + (size_t)br * 768 * 768;
    const int c = threadIdx.x * 4;
    float4 v = *(const float4*)&W[(size_t)row * 768 + c];
    size_t o = ((size_t)mat * 768 + row) * 768 + c;
    uint32_t h0 = packh(v.x, v.y), h1 = packh(v.z, v.w);
    *(uint32_t*)&g_Wh[o]     = h0;
    *(uint32_t*)&g_Wh[o + 2] = h1;
    *(uint32_t*)&g_Wm[o]     = packm(v.x, v.y, h0);
    *(uint32_t*)&g_Wm[o + 2] = packm(v.z, v.w, h1);
}

// ------------------------------------------------------------------
// Kernel 2: projection GEMM, bf16 3-pass warp-mma, cp.async 2-stage.
// CTA = 128x128 tile of one of 9 matrices. K-chunk 32, 24 chunks.
// ------------------------------------------------------------------
#define P_PLANE 5120                 // 128*40 bf16 elems per plane
#define SA_(st, pl) ((__nv_bfloat16(*)[40])(ps + ((st) * 2 + (pl)) * P_PLANE))
#define SB_(st, pl) ((__nv_bfloat16(*)[40])(ps + (4 + (st) * 2 + (pl)) * P_PLANE))
#define P_SMEM (8 * P_PLANE * 2)     // 81920 B

__global__ __launch_bounds__(256, 2) void proj_mma(
    const float* __restrict__ bq, const float* __restrict__ bk, const float* __restrict__ bv)
{
    extern __shared__ __nv_bfloat16 ps[];
    const int mat = blockIdx.z, br = mat % 3, typ = mat / 3;
    const int rt = blockIdx.x, ct = blockIdx.y;
    const int tid = threadIdx.x, lane = tid & 31, warp = tid >> 5;
    const int wr = warp >> 1, wc = warp & 1;
    const int l7 = lane & 7, l8 = lane & 8, l16 = (lane & 16) >> 1;

    const __nv_bfloat16* Ap[2] = {
        g_xh + ((size_t)br * 8192 + rt * 128) * 768,
        g_xm + ((size_t)br * 8192 + rt * 128) * 768 };
    const __nv_bfloat16* Bp[2] = {
        g_Wh + ((size_t)mat * 768 + ct * 128) * 768,
        g_Wm + ((size_t)mat * 768 + ct * 128) * 768 };

    float acc[2][8][4];
#pragma unroll
    for (int i = 0; i < 2; ++i)
#pragma unroll
        for (int j = 0; j < 8; ++j)
#pragma unroll
            for (int k = 0; k < 4; ++k) acc[i][j][k] = 0.f;

    auto load_chunk = [&](int kt, int st) {
#pragma unroll
        for (int i = 0; i < 4; ++i) {            // A: 2 planes x 128 rows x 4 segs
            int idx = i * 256 + tid;
            int seg = idx & 3, row = (idx >> 2) & 127, pl = idx >> 9;
            cp16(smaddr(&SA_(st, pl)[row][seg * 8]),
                 Ap[pl] + (size_t)row * 768 + kt * 32 + seg * 8);
        }
#pragma unroll
        for (int i = 0; i < 4; ++i) {            // B
            int idx = i * 256 + tid;
            int seg = idx & 3, row = (idx >> 2) & 127, pl = idx >> 9;
            cp16(smaddr(&SB_(st, pl)[row][seg * 8]),
                 Bp[pl] + (size_t)row * 768 + kt * 32 + seg * 8);
        }
    };

    load_chunk(0, 0);
    cp_commit();

    for (int kt = 0; kt < 24; ++kt) {
        const int st = kt & 1;
        if (kt < 23) { load_chunk(kt + 1, st ^ 1); cp_commit(); cp_wait1(); }
        else cp_wait0();
        __syncthreads();

        __nv_bfloat16 (*sAh)[40] = SA_(st, 0), (*sAm)[40] = SA_(st, 1);
        __nv_bfloat16 (*sBh)[40] = SB_(st, 0), (*sBm)[40] = SB_(st, 1);
#pragma unroll
        for (int ks = 0; ks < 2; ++ks) {
            const int k0 = ks * 16;
            uint32_t ah[2][4], am_[2][4];
#pragma unroll
            for (int mt = 0; mt < 2; ++mt) {
                int r0 = wr * 32 + mt * 16 + l7 + l8;
                ldsm4(ah[mt],  smaddr(&sAh[r0][k0 + l16]));
                ldsm4(am_[mt], smaddr(&sAm[r0][k0 + l16]));
            }
#pragma unroll
            for (int p = 0; p < 4; ++p) {
                int n0 = wc * 64 + p * 16 + l7 + l16;
                uint32_t bh[4], bm_[4];
                ldsm4(bh,  smaddr(&sBh[n0][k0 + l8]));
                ldsm4(bm_, smaddr(&sBm[n0][k0 + l8]));
#pragma unroll
                for (int mt = 0; mt < 2; ++mt) {
                    mma16(acc[mt][2 * p],     ah[mt],  bh);
                    mma16(acc[mt][2 * p],     ah[mt],  bm_);
                    mma16(acc[mt][2 * p],     am_[mt], bh);
                    mma16(acc[mt][2 * p + 1], ah[mt],  bh + 2);
                    mma16(acc[mt][2 * p + 1], ah[mt],  bm_ + 2);
                    mma16(acc[mt][2 * p + 1], am_[mt], bh + 2);
                }
            }
        }
        __syncthreads();
    }

    // epilogue: bias, split to bf16 hi/mid planes [br][b][h][n][64]
    const float* Bb = (typ == 0 ? bq : typ == 1 ? bk : bv) + br * 768;
    __nv_bfloat16* dh = (typ == 0 ? g_Qh : typ == 1 ? g_Kh : g_Vh);
    __nv_bfloat16* dm = (typ == 0 ? g_Qm : typ == 1 ? g_Km : g_Vm);
    const int h  = ct * 2 + wc;
    const int bb = (rt * 128) >> 10;
    const int nb = (rt * 128) & 1023;
    const int tg = lane & 3, g = lane >> 2;
#pragma unroll
    for (int mt = 0; mt < 2; ++mt) {
        int r = wr * 32 + mt * 16 + g;
#pragma unroll
        for (int nt = 0; nt < 8; ++nt) {
            int d = nt * 8 + tg * 2;
            float2 bi = *(const float2*)&Bb[h * 64 + d];
            float v0 = acc[mt][nt][0] + bi.x, v1 = acc[mt][nt][1] + bi.y;
            float v2 = acc[mt][nt][2] + bi.x, v3 = acc[mt][nt][3] + bi.y;
            size_t base = ((((size_t)br * 8 + bb) * 12 + h) * 1024 + (nb + r)) * 64 + d;
            uint32_t h0 = packh(v0, v1), h1 = packh(v2, v3);
            *(uint32_t*)&dh[base]          = h0;
            *(uint32_t*)&dh[base + 8 * 64] = h1;
            *(uint32_t*)&dm[base]          = packm(v0, v1, h0);
            *(uint32_t*)&dm[base + 8 * 64] = packm(v2, v3, h1);
        }
    }
}

// ------------------------------------------------------------------
// Kernel 3: flash attention, bf16 3-pass, cp.async 2-stage K/V pipeline.
// ------------------------------------------------------------------
#define A_PLANE 9216                 // 128*72 elems
#define SKV_(st, pl) ((__nv_bfloat16(*)[72])(as_ + 2 * A_PLANE + ((st) * 4 + (pl)) * A_PLANE))
#define A_SMEM ((2 + 8) * A_PLANE * 2)   // 184320 B

__global__ __launch_bounds__(256) void attn_kernel(float* __restrict__ out) {
    extern __shared__ __nv_bfloat16 as_[];
    __nv_bfloat16 (*sQh)[72] = (__nv_bfloat16(*)[72])(as_);
    __nv_bfloat16 (*sQm)[72] = (__nv_bfloat16(*)[72])(as_ + A_PLANE);

    const int qt = blockIdx.x, h = blockIdx.y, bb = blockIdx.z;
    const int tid = threadIdx.x, lane = tid & 31, warp = tid >> 5;
    const int g = lane >> 2, tg = lane & 3;
    const int l7 = lane & 7, l8 = lane & 8, l16 = (lane & 16) >> 1;
    const int r0 = warp * 16 + g;

    for (int brn = 0; brn < 3; ++brn) {
        const size_t hb = (((size_t)brn * 8 + bb) * 12 + h) * (size_t)(1024 * 64);
        const __nv_bfloat16* KVp[4] = { g_Kh + hb, g_Km + hb, g_Vh + hb, g_Vm + hb };
        const __nv_bfloat16* Qp[2]  = { g_Qh + hb + (size_t)qt * 128 * 64,
                                        g_Qm + hb + (size_t)qt * 128 * 64 };

        auto loadKV = [&](int jt, int st) {
#pragma unroll
            for (int i = 0; i < 16; ++i) {
                int idx = i * 256 + tid;
                int seg = idx & 7, row = (idx >> 3) & 127, pl = idx >> 10;
                cp16(smaddr(&SKV_(st, pl)[row][seg * 8]),
                     KVp[pl] + (size_t)(jt * 128 + row) * 64 + seg * 8);
            }
        };

        // prologue: Q + KV tile 0 in one group
#pragma unroll
        for (int i = 0; i < 8; ++i) {
            int idx = i * 256 + tid;
            int seg = idx & 7, row = (idx >> 3) & 127, pl = idx >> 10;
            cp16(smaddr(&(pl ? sQm : sQh)[row][seg * 8]),
                 Qp[pl] + (size_t)row * 64 + seg * 8);
        }
        loadKV(0, 0);
        cp_commit();

        float m0 = -1e30f, m1 = -1e30f, l0 = 0.f, l1 = 0.f;
        float oa[8][4];
#pragma unroll
        for (int i = 0; i < 8; ++i)
#pragma unroll
            for (int j = 0; j < 4; ++j) oa[i][j] = 0.f;

        for (int jt = 0; jt < 8; ++jt) {
            const int st = jt & 1;
            if (jt < 7) { loadKV(jt + 1, st ^ 1); cp_commit(); cp_wait1(); }
            else cp_wait0();
            __syncthreads();

            __nv_bfloat16 (*sKh)[72] = SKV_(st, 0), (*sKm)[72] = SKV_(st, 1);
            __nv_bfloat16 (*sVh)[72] = SKV_(st, 2), (*sVm)[72] = SKV_(st, 3);

            // ---- S = Q K^T : 16 rows x 128 cols per warp ----
            float sf[16][4];
#pragma unroll
            for (int i = 0; i < 16; ++i)
#pragma unroll
                for (int j = 0; j < 4; ++j) sf[i][j] = 0.f;
#pragma unroll
            for (int ks = 0; ks < 4; ++ks) {
                const int k0 = ks * 16;
                uint32_t qh[4], qm[4];
                ldsm4(qh, smaddr(&sQh[warp * 16 + l7 + l8][k0 + l16]));
                ldsm4(qm, smaddr(&sQm[warp * 16 + l7 + l8][k0 + l16]));
#pragma unroll
                for (int p = 0; p < 8; ++p) {
                    int n0 = p * 16 + l7 + l16;
                    uint32_t kh_[4], km_[4];
                    ldsm4(kh_, smaddr(&sKh[n0][k0 + l8]));
                    ldsm4(km_, smaddr(&sKm[n0][k0 + l8]));
                    mma16(sf[2 * p],     qh, kh_);
                    mma16(sf[2 * p],     qh, km_);
                    mma16(sf[2 * p],     qm, kh_);
                    mma16(sf[2 * p + 1], qh, kh_ + 2);
                    mma16(sf[2 * p + 1], qh, km_ + 2);
                    mma16(sf[2 * p + 1], qm, kh_ + 2);
                }
            }

            // ---- online softmax ----
            float t0 = -1e30f, t1 = -1e30f;
#pragma unroll
            for (int nt = 0; nt < 16; ++nt) {
                t0 = fmaxf(t0, fmaxf(sf[nt][0], sf[nt][1]));
                t1 = fmaxf(t1, fmaxf(sf[nt][2], sf[nt][3]));
            }
            t0 = fmaxf(t0, __shfl_xor_sync(0xffffffffu, t0, 1));
            t0 = fmaxf(t0, __shfl_xor_sync(0xffffffffu, t0, 2));
            t1 = fmaxf(t1, __shfl_xor_sync(0xffffffffu, t1, 1));
            t1 = fmaxf(t1, __shfl_xor_sync(0xffffffffu, t1, 2));
            float mn0 = fmaxf(m0, t0), mn1 = fmaxf(m1, t1);
            float a0 = __expf(m0 - mn0), a1 = __expf(m1 - mn1);
            m0 = mn0; m1 = mn1;

            float rs0 = 0.f, rs1 = 0.f;
#pragma unroll
            for (int nt = 0; nt < 16; ++nt) {
                sf[nt][0] = __expf(sf[nt][0] - mn0);
                sf[nt][1] = __expf(sf[nt][1] - mn0);
                sf[nt][2] = __expf(sf[nt][2] - mn1);
                sf[nt][3] = __expf(sf[nt][3] - mn1);
                rs0 += sf[nt][0] + sf[nt][1];
                rs1 += sf[nt][2] + sf[nt][3];
            }
            l0 = l0 * a0 + rs0;
            l1 = l1 * a1 + rs1;
#pragma unroll
            for (int nt = 0; nt < 8; ++nt) {
                oa[nt][0] *= a0; oa[nt][1] *= a0;
                oa[nt][2] *= a1; oa[nt][3] *= a1;
            }

            // ---- O += P V : P fragments built in registers from sf ----
#pragma unroll
            for (int ks = 0; ks < 8; ++ks) {
                uint32_t ph[4], pm[4];
                ph[0] = packh(sf[2 * ks][0],     sf[2 * ks][1]);
                ph[1] = packh(sf[2 * ks][2],     sf[2 * ks][3]);
                ph[2] = packh(sf[2 * ks + 1][0], sf[2 * ks + 1][1]);
                ph[3] = packh(sf[2 * ks + 1][2], sf[2 * ks + 1][3]);
                pm[0] = packm(sf[2 * ks][0],     sf[2 * ks][1],     ph[0]);
                pm[1] = packm(sf[2 * ks][2],     sf[2 * ks][3],     ph[1]);
                pm[2] = packm(sf[2 * ks + 1][0], sf[2 * ks + 1][1], ph[2]);
                pm[3] = packm(sf[2 * ks + 1][2], sf[2 * ks + 1][3], ph[3]);
                const int kv0 = ks * 16 + l7 + l8;
#pragma unroll
                for (int p = 0; p < 4; ++p) {
                    int d0 = p * 16 + l16;
                    uint32_t vh_[4], vm_[4];
                    ldsm4t(vh_, smaddr(&sVh[kv0][d0]));
                    ldsm4t(vm_, smaddr(&sVm[kv0][d0]));
                    mma16(oa[2 * p],     ph, vh_);
                    mma16(oa[2 * p],     ph, vm_);
                    mma16(oa[2 * p],     pm, vh_);
                    mma16(oa[2 * p + 1], ph, vh_ + 2);
                    mma16(oa[2 * p + 1], ph, vm_ + 2);
                    mma16(oa[2 * p + 1], pm, vh_ + 2);
                }
            }
            __syncthreads();
        }

        // fold branch into out (RMW; CTA owns its tile across branches)
        float L0 = l0 + __shfl_xor_sync(0xffffffffu, l0, 1);
        L0 += __shfl_xor_sync(0xffffffffu, L0, 2);
        float L1 = l1 + __shfl_xor_sync(0xffffffffu, l1, 1);
        L1 += __shfl_xor_sync(0xffffffffu, L1, 2);
        float i0 = 1.f / L0, i1 = 1.f / L1;
#pragma unroll
        for (int nt = 0; nt < 8; ++nt) {
            int d = nt * 8 + tg * 2;
            size_t base = ((size_t)bb * 1024 + (size_t)(qt * 128 + r0)) * 768 + h * 64 + d;
            float2 v0 = make_float2(oa[nt][0] * i0, oa[nt][1] * i0);
            float2 v1 = make_float2(oa[nt][2] * i1, oa[nt][3] * i1);
            if (brn) {
                float2 o0 = *(float2*)&out[base];
                float2 o1 = *(float2*)&out[base + (size_t)8 * 768];
                v0.x += o0.x; v0.y += o0.y; v1.x += o1.x; v1.y += o1.y;
            }
            *(float2*)&out[base]                   = v0;
            *(float2*)&out[base + (size_t)8 * 768] = v1;
        }
    }
}

// ------------------------------------------------------------------
extern "C" void kernel_launch(void* const* d_in, const int* in_sizes, int n_in,
                              void* d_out, int out_size) {
    (void)in_sizes; (void)n_in; (void)out_size;
    const float* x  = (const float*)d_in[0];
    const float* wq = (const float*)d_in[1];
    const float* bq = (const float*)d_in[2];
    const float* wk = (const float*)d_in[3];
    const float* bk = (const float*)d_in[4];
    const float* wv = (const float*)d_in[5];
    const float* bv = (const float*)d_in[6];
    float* out = (float*)d_out;

    scales_kernel<<<8192, 256>>>(x);
    prep_x<<<dim3(8192, 3), 192>>>(x);
    prep_w<<<dim3(768, 9), 192>>>(wq, wk, wv);

    cudaFuncSetAttribute(proj_mma, cudaFuncAttributeMaxDynamicSharedMemorySize, P_SMEM);
    proj_mma<<<dim3(64, 6, 9), 256, P_SMEM>>>(bq, bk, bv);

    cudaFuncSetAttribute(attn_kernel, cudaFuncAttributeMaxDynamicSharedMemorySize, A_SMEM);
    attn_kernel<<<dim3(8, 12, 8), 256, A_SMEM>>>(out);
}

// round 6
// speedup vs baseline: 2.5637x; 1.0190x over previous
#include <cuda_runtime.h>
#include <cuda_bf16.h>
#include <cstdint>
#include <cstddef>

#define DEVI __device__ __forceinline__

// ------------------------------------------------------------------
// Scratch (__device__ globals; allocation-free rule)
// ------------------------------------------------------------------
__device__ float g_scale[2][8192];
__device__ __nv_bfloat16 g_xh[3ull * 8192 * 768];
__device__ __nv_bfloat16 g_xm[3ull * 8192 * 768];
__device__ __nv_bfloat16 g_Wh[9ull * 768 * 768];
__device__ __nv_bfloat16 g_Wm[9ull * 768 * 768];
__device__ __nv_bfloat16 g_Qh[3ull * 8 * 12 * 1024 * 64];
__device__ __nv_bfloat16 g_Qm[3ull * 8 * 12 * 1024 * 64];
__device__ __nv_bfloat16 g_Kh[3ull * 8 * 12 * 1024 * 64];
__device__ __nv_bfloat16 g_Km[3ull * 8 * 12 * 1024 * 64];
__device__ __nv_bfloat16 g_Vh[3ull * 8 * 12 * 1024 * 64];
__device__ __nv_bfloat16 g_Vm[3ull * 8 * 12 * 1024 * 64];

// ------------------------------------------------------------------
// Helpers
// ------------------------------------------------------------------
DEVI uint32_t smaddr(const void* p) { return (uint32_t)__cvta_generic_to_shared(p); }

DEVI uint32_t packh(float a, float b) {
    __nv_bfloat16 ha = __float2bfloat16(a), hb = __float2bfloat16(b);
    uint16_t ua, ub;
    memcpy(&ua, &ha, 2); memcpy(&ub, &hb, 2);
    return ((uint32_t)ub << 16) | ua;
}
DEVI uint32_t packm(float a, float b, uint32_t h) {
    uint16_t ua = (uint16_t)(h & 0xffffu), ub = (uint16_t)(h >> 16);
    __nv_bfloat16 ha, hb;
    memcpy(&ha, &ua, 2); memcpy(&hb, &ub, 2);
    return packh(a - __bfloat162float(ha), b - __bfloat162float(hb));
}

DEVI void cp16(uint32_t dst, const void* src) {
    asm volatile("cp.async.cg.shared.global [%0], [%1], 16;" :: "r"(dst), "l"(src) : "memory");
}
DEVI void cp_commit() { asm volatile("cp.async.commit_group;" ::: "memory"); }
DEVI void cp_wait0()  { asm volatile("cp.async.wait_group 0;" ::: "memory"); }
DEVI void cp_wait1()  { asm volatile("cp.async.wait_group 1;" ::: "memory"); }

DEVI void ldsm4(uint32_t r[4], uint32_t a) {
    asm volatile("ldmatrix.sync.aligned.m8n8.x4.shared.b16 {%0,%1,%2,%3}, [%4];"
                 : "=r"(r[0]), "=r"(r[1]), "=r"(r[2]), "=r"(r[3]) : "r"(a));
}
DEVI void ldsm4t(uint32_t r[4], uint32_t a) {
    asm volatile("ldmatrix.sync.aligned.m8n8.x4.trans.shared.b16 {%0,%1,%2,%3}, [%4];"
                 : "=r"(r[0]), "=r"(r[1]), "=r"(r[2]), "=r"(r[3]) : "r"(a));
}
DEVI void mma16(float d[4], const uint32_t a[4], const uint32_t b[2]) {
    asm volatile(
        "mma.sync.aligned.m16n8k16.row.col.f32.bf16.bf16.f32 "
        "{%0,%1,%2,%3}, {%4,%5,%6,%7}, {%8,%9}, {%0,%1,%2,%3};"
        : "+f"(d[0]), "+f"(d[1]), "+f"(d[2]), "+f"(d[3])
        : "r"(a[0]), "r"(a[1]), "r"(a[2]), "r"(a[3]), "r"(b[0]), "r"(b[1]));
}

// ------------------------------------------------------------------
// Kernel 1: per-row branch scalars (all 3 geometric maps are s(|x|)*x)
// ------------------------------------------------------------------
__global__ __launch_bounds__(256) void scales_kernel(const float* __restrict__ x) {
    __shared__ float red[8];
    const int row = blockIdx.x;
    const float* xr = x + (size_t)row * 768;
    float ss = 0.f;
    for (int i = threadIdx.x; i < 768; i += 256) { float v = xr[i]; ss = fmaf(v, v, ss); }
#pragma unroll
    for (int o = 16; o; o >>= 1) ss += __shfl_xor_sync(0xffffffffu, ss, o);
    if ((threadIdx.x & 31) == 0) red[threadIdx.x >> 5] = ss;
    __syncthreads();
    if (threadIdx.x == 0) {
        float t = 0.f;
#pragma unroll
        for (int i = 0; i < 8; ++i) t += red[i];
        float n = fmaxf(sqrtf(t), 1e-5f);
        const float sc = 0.316227766016837933f;     // sqrt(0.1)
        float a = sc * n;
        float th = tanhf(a);
        float s_pre = th / a;
        float norm_h = th / sc;
        float maxn = (1.0f - 4e-3f) / sc;
        float s_h = (norm_h > maxn) ? s_pre * (maxn / norm_h) : s_pre;
        float arg = fminf(a, 1.0f - 1e-5f);
        float art = 0.5f * logf((1.0f + arg) / (1.0f - arg));
        float s_s = art / (n * sc);
        g_scale[0][row] = s_h;
        g_scale[1][row] = s_s;
    }
}

// ------------------------------------------------------------------
// Kernel 1b/1c: pre-split branch-scaled x and weights into bf16 planes
// ------------------------------------------------------------------
__global__ __launch_bounds__(192) void prep_x(const float* __restrict__ x) {
    const int row = blockIdx.x, br = blockIdx.y;
    const float s = (br == 0) ? 1.0f : g_scale[br - 1][row];
    const int c = threadIdx.x * 4;
    float4 v = *(const float4*)&x[(size_t)row * 768 + c];
    v.x *= s; v.y *= s; v.z *= s; v.w *= s;
    size_t o = ((size_t)br * 8192 + row) * 768 + c;
    uint32_t h0 = packh(v.x, v.y), h1 = packh(v.z, v.w);
    *(uint32_t*)&g_xh[o]     = h0;
    *(uint32_t*)&g_xh[o + 2] = h1;
    *(uint32_t*)&g_xm[o]     = packm(v.x, v.y, h0);
    *(uint32_t*)&g_xm[o + 2] = packm(v.z, v.w, h1);
}

__global__ __launch_bounds__(192) void prep_w(
    const float* __restrict__ wq, const float* __restrict__ wk, const float* __restrict__ wv) {
    const int row = blockIdx.x, mat = blockIdx.y;
    const int typ = mat / 3, br = mat % 3;
    const float* W = (typ == 0 ? wq : typ == 1 ? wk : wv) + (size_t)br * 768 * 768;
    const int c = threadIdx.x * 4;
    float4 v = *(const float4*)&W[(size_t)row * 768 + c];
    size_t o = ((size_t)mat * 768 + row) * 768 + c;
    uint32_t h0 = packh(v.x, v.y), h1 = packh(v.z, v.w);
    *(uint32_t*)&g_Wh[o]     = h0;
    *(uint32_t*)&g_Wh[o + 2] = h1;
    *(uint32_t*)&g_Wm[o]     = packm(v.x, v.y, h0);
    *(uint32_t*)&g_Wm[o + 2] = packm(v.z, v.w, h1);
}

// ------------------------------------------------------------------
// Kernel 2: projection GEMM, bf16 3-pass warp-mma, cp.async 2-stage.
// Pass-major MMA ordering: 16 distinct accumulators per sweep.
// ------------------------------------------------------------------
#define P_PLANE 5120                 // 128*40 bf16 elems per plane
#define SA_(st, pl) ((__nv_bfloat16(*)[40])(ps + ((st) * 2 + (pl)) * P_PLANE))
#define SB_(st, pl) ((__nv_bfloat16(*)[40])(ps + (4 + (st) * 2 + (pl)) * P_PLANE))
#define P_SMEM (8 * P_PLANE * 2)     // 81920 B

__global__ __launch_bounds__(256, 2) void proj_mma(
    const float* __restrict__ bq, const float* __restrict__ bk, const float* __restrict__ bv)
{
    extern __shared__ __nv_bfloat16 ps[];
    const int mat = blockIdx.z, br = mat % 3, typ = mat / 3;
    const int rt = blockIdx.x, ct = blockIdx.y;
    const int tid = threadIdx.x, lane = tid & 31, warp = tid >> 5;
    const int wr = warp >> 1, wc = warp & 1;
    const int l7 = lane & 7, l8 = lane & 8, l16 = (lane & 16) >> 1;

    const __nv_bfloat16* Ap[2] = {
        g_xh + ((size_t)br * 8192 + rt * 128) * 768,
        g_xm + ((size_t)br * 8192 + rt * 128) * 768 };
    const __nv_bfloat16* Bp[2] = {
        g_Wh + ((size_t)mat * 768 + ct * 128) * 768,
        g_Wm + ((size_t)mat * 768 + ct * 128) * 768 };

    float acc[2][8][4];
#pragma unroll
    for (int i = 0; i < 2; ++i)
#pragma unroll
        for (int j = 0; j < 8; ++j)
#pragma unroll
            for (int k = 0; k < 4; ++k) acc[i][j][k] = 0.f;

    auto load_chunk = [&](int kt, int st) {
#pragma unroll
        for (int i = 0; i < 4; ++i) {
            int idx = i * 256 + tid;
            int seg = idx & 3, row = (idx >> 2) & 127, pl = idx >> 9;
            cp16(smaddr(&SA_(st, pl)[row][seg * 8]),
                 Ap[pl] + (size_t)row * 768 + kt * 32 + seg * 8);
        }
#pragma unroll
        for (int i = 0; i < 4; ++i) {
            int idx = i * 256 + tid;
            int seg = idx & 3, row = (idx >> 2) & 127, pl = idx >> 9;
            cp16(smaddr(&SB_(st, pl)[row][seg * 8]),
                 Bp[pl] + (size_t)row * 768 + kt * 32 + seg * 8);
        }
    };

    load_chunk(0, 0);
    cp_commit();

    for (int kt = 0; kt < 24; ++kt) {
        const int st = kt & 1;
        if (kt < 23) { load_chunk(kt + 1, st ^ 1); cp_commit(); cp_wait1(); }
        else cp_wait0();
        __syncthreads();

        __nv_bfloat16 (*sAh)[40] = SA_(st, 0), (*sAm)[40] = SA_(st, 1);
        __nv_bfloat16 (*sBh)[40] = SB_(st, 0), (*sBm)[40] = SB_(st, 1);
#pragma unroll
        for (int ks = 0; ks < 2; ++ks) {
            const int k0 = ks * 16;
            // hoist all fragments
            uint32_t ah[2][4], am_[2][4];
#pragma unroll
            for (int mt = 0; mt < 2; ++mt) {
                int r0 = wr * 32 + mt * 16 + l7 + l8;
                ldsm4(ah[mt],  smaddr(&sAh[r0][k0 + l16]));
                ldsm4(am_[mt], smaddr(&sAm[r0][k0 + l16]));
            }
            uint32_t bh[4][4], bm_[4][4];
#pragma unroll
            for (int p = 0; p < 4; ++p) {
                int n0 = wc * 64 + p * 16 + l7 + l16;
                ldsm4(bh[p],  smaddr(&sBh[n0][k0 + l8]));
                ldsm4(bm_[p], smaddr(&sBm[n0][k0 + l8]));
            }
            // pass hh (16 distinct acc targets)
#pragma unroll
            for (int p = 0; p < 4; ++p)
#pragma unroll
                for (int mt = 0; mt < 2; ++mt) {
                    mma16(acc[mt][2 * p],     ah[mt], bh[p]);
                    mma16(acc[mt][2 * p + 1], ah[mt], bh[p] + 2);
                }
            // pass hm
#pragma unroll
            for (int p = 0; p < 4; ++p)
#pragma unroll
                for (int mt = 0; mt < 2; ++mt) {
                    mma16(acc[mt][2 * p],     ah[mt], bm_[p]);
                    mma16(acc[mt][2 * p + 1], ah[mt], bm_[p] + 2);
                }
            // pass mh
#pragma unroll
            for (int p = 0; p < 4; ++p)
#pragma unroll
                for (int mt = 0; mt < 2; ++mt) {
                    mma16(acc[mt][2 * p],     am_[mt], bh[p]);
                    mma16(acc[mt][2 * p + 1], am_[mt], bh[p] + 2);
                }
        }
        __syncthreads();
    }

    // epilogue: bias, split to bf16 hi/mid planes [br][b][h][n][64]
    const float* Bb = (typ == 0 ? bq : typ == 1 ? bk : bv) + br * 768;
    __nv_bfloat16* dh = (typ == 0 ? g_Qh : typ == 1 ? g_Kh : g_Vh);
    __nv_bfloat16* dm = (typ == 0 ? g_Qm : typ == 1 ? g_Km : g_Vm);
    const int h  = ct * 2 + wc;
    const int bb = (rt * 128) >> 10;
    const int nb = (rt * 128) & 1023;
    const int tg = lane & 3, g = lane >> 2;
#pragma unroll
    for (int mt = 0; mt < 2; ++mt) {
        int r = wr * 32 + mt * 16 + g;
#pragma unroll
        for (int nt = 0; nt < 8; ++nt) {
            int d = nt * 8 + tg * 2;
            float2 bi = *(const float2*)&Bb[h * 64 + d];
            float v0 = acc[mt][nt][0] + bi.x, v1 = acc[mt][nt][1] + bi.y;
            float v2 = acc[mt][nt][2] + bi.x, v3 = acc[mt][nt][3] + bi.y;
            size_t base = ((((size_t)br * 8 + bb) * 12 + h) * 1024 + (nb + r)) * 64 + d;
            uint32_t h0 = packh(v0, v1), h1 = packh(v2, v3);
            *(uint32_t*)&dh[base]          = h0;
            *(uint32_t*)&dh[base + 8 * 64] = h1;
            *(uint32_t*)&dm[base]          = packm(v0, v1, h0);
            *(uint32_t*)&dm[base + 8 * 64] = packm(v2, v3, h1);
        }
    }
}

// ------------------------------------------------------------------
// Kernel 3: flash attention, bf16 3-pass, 64-row KV tiles, 2 CTAs/SM,
// pass-major MMA ordering.
// ------------------------------------------------------------------
#define AQ_PLANE 9216                // 128*72
#define AKV_PLANE 4608               // 64*72
#define SKV_(st, pl) ((__nv_bfloat16(*)[72])(as_ + 2 * AQ_PLANE + ((st) * 4 + (pl)) * AKV_PLANE))
#define A_SMEM ((2 * AQ_PLANE + 8 * AKV_PLANE) * 2)   // 110592 B

__global__ __launch_bounds__(256, 2) void attn_kernel(float* __restrict__ out) {
    extern __shared__ __nv_bfloat16 as_[];
    __nv_bfloat16 (*sQh)[72] = (__nv_bfloat16(*)[72])(as_);
    __nv_bfloat16 (*sQm)[72] = (__nv_bfloat16(*)[72])(as_ + AQ_PLANE);

    const int qt = blockIdx.x, h = blockIdx.y, bb = blockIdx.z;
    const int tid = threadIdx.x, lane = tid & 31, warp = tid >> 5;
    const int g = lane >> 2, tg = lane & 3;
    const int l7 = lane & 7, l8 = lane & 8, l16 = (lane & 16) >> 1;
    const int r0 = warp * 16 + g;

    for (int brn = 0; brn < 3; ++brn) {
        const size_t hb = (((size_t)brn * 8 + bb) * 12 + h) * (size_t)(1024 * 64);
        const __nv_bfloat16* KVp[4] = { g_Kh + hb, g_Km + hb, g_Vh + hb, g_Vm + hb };
        const __nv_bfloat16* Qp[2]  = { g_Qh + hb + (size_t)qt * 128 * 64,
                                        g_Qm + hb + (size_t)qt * 128 * 64 };

        auto loadKV = [&](int jt, int st) {
#pragma unroll
            for (int i = 0; i < 8; ++i) {
                int idx = i * 256 + tid;
                int seg = idx & 7, row = (idx >> 3) & 63, pl = idx >> 9;
                cp16(smaddr(&SKV_(st, pl)[row][seg * 8]),
                     KVp[pl] + (size_t)(jt * 64 + row) * 64 + seg * 8);
            }
        };

        // prologue: Q + KV tile 0 in one group
#pragma unroll
        for (int i = 0; i < 8; ++i) {
            int idx = i * 256 + tid;
            int seg = idx & 7, row = (idx >> 3) & 127, pl = idx >> 10;
            cp16(smaddr(&(pl ? sQm : sQh)[row][seg * 8]),
                 Qp[pl] + (size_t)row * 64 + seg * 8);
        }
        loadKV(0, 0);
        cp_commit();

        float m0 = -1e30f, m1 = -1e30f, l0 = 0.f, l1 = 0.f;
        float oa[8][4];
#pragma unroll
        for (int i = 0; i < 8; ++i)
#pragma unroll
            for (int j = 0; j < 4; ++j) oa[i][j] = 0.f;

        for (int jt = 0; jt < 16; ++jt) {
            const int st = jt & 1;
            if (jt < 15) { loadKV(jt + 1, st ^ 1); cp_commit(); cp_wait1(); }
            else cp_wait0();
            __syncthreads();

            __nv_bfloat16 (*sKh)[72] = SKV_(st, 0), (*sKm)[72] = SKV_(st, 1);
            __nv_bfloat16 (*sVh)[72] = SKV_(st, 2), (*sVm)[72] = SKV_(st, 3);

            // ---- S = Q K^T : 16 q-rows x 64 kv-cols per warp ----
            float sf[8][4];
#pragma unroll
            for (int i = 0; i < 8; ++i)
#pragma unroll
                for (int j = 0; j < 4; ++j) sf[i][j] = 0.f;
#pragma unroll
            for (int ks = 0; ks < 4; ++ks) {
                const int k0 = ks * 16;
                uint32_t qh[4], qm[4];
                ldsm4(qh, smaddr(&sQh[warp * 16 + l7 + l8][k0 + l16]));
                ldsm4(qm, smaddr(&sQm[warp * 16 + l7 + l8][k0 + l16]));
                uint32_t kh_[4][4], km_[4][4];
#pragma unroll
                for (int p = 0; p < 4; ++p) {
                    int n0 = p * 16 + l7 + l16;
                    ldsm4(kh_[p], smaddr(&sKh[n0][k0 + l8]));
                    ldsm4(km_[p], smaddr(&sKm[n0][k0 + l8]));
                }
#pragma unroll
                for (int p = 0; p < 4; ++p) {
                    mma16(sf[2 * p],     qh, kh_[p]);
                    mma16(sf[2 * p + 1], qh, kh_[p] + 2);
                }
#pragma unroll
                for (int p = 0; p < 4; ++p) {
                    mma16(sf[2 * p],     qh, km_[p]);
                    mma16(sf[2 * p + 1], qh, km_[p] + 2);
                }
#pragma unroll
                for (int p = 0; p < 4; ++p) {
                    mma16(sf[2 * p],     qm, kh_[p]);
                    mma16(sf[2 * p + 1], qm, kh_[p] + 2);
                }
            }

            // ---- online softmax ----
            float t0 = -1e30f, t1 = -1e30f;
#pragma unroll
            for (int nt = 0; nt < 8; ++nt) {
                t0 = fmaxf(t0, fmaxf(sf[nt][0], sf[nt][1]));
                t1 = fmaxf(t1, fmaxf(sf[nt][2], sf[nt][3]));
            }
            t0 = fmaxf(t0, __shfl_xor_sync(0xffffffffu, t0, 1));
            t0 = fmaxf(t0, __shfl_xor_sync(0xffffffffu, t0, 2));
            t1 = fmaxf(t1, __shfl_xor_sync(0xffffffffu, t1, 1));
            t1 = fmaxf(t1, __shfl_xor_sync(0xffffffffu, t1, 2));
            float mn0 = fmaxf(m0, t0), mn1 = fmaxf(m1, t1);
            float a0 = __expf(m0 - mn0), a1 = __expf(m1 - mn1);
            m0 = mn0; m1 = mn1;

            float rs0 = 0.f, rs1 = 0.f;
#pragma unroll
            for (int nt = 0; nt < 8; ++nt) {
                sf[nt][0] = __expf(sf[nt][0] - mn0);
                sf[nt][1] = __expf(sf[nt][1] - mn0);
                sf[nt][2] = __expf(sf[nt][2] - mn1);
                sf[nt][3] = __expf(sf[nt][3] - mn1);
                rs0 += sf[nt][0] + sf[nt][1];
                rs1 += sf[nt][2] + sf[nt][3];
            }
            l0 = l0 * a0 + rs0;
            l1 = l1 * a1 + rs1;
#pragma unroll
            for (int nt = 0; nt < 8; ++nt) {
                oa[nt][0] *= a0; oa[nt][1] *= a0;
                oa[nt][2] *= a1; oa[nt][3] *= a1;
            }

            // ---- O += P V (P fragments in registers; pass-major) ----
#pragma unroll
            for (int ks = 0; ks < 4; ++ks) {
                uint32_t ph[4], pm[4];
                ph[0] = packh(sf[2 * ks][0],     sf[2 * ks][1]);
                ph[1] = packh(sf[2 * ks][2],     sf[2 * ks][3]);
                ph[2] = packh(sf[2 * ks + 1][0], sf[2 * ks + 1][1]);
                ph[3] = packh(sf[2 * ks + 1][2], sf[2 * ks + 1][3]);
                pm[0] = packm(sf[2 * ks][0],     sf[2 * ks][1],     ph[0]);
                pm[1] = packm(sf[2 * ks][2],     sf[2 * ks][3],     ph[1]);
                pm[2] = packm(sf[2 * ks + 1][0], sf[2 * ks + 1][1], ph[2]);
                pm[3] = packm(sf[2 * ks + 1][2], sf[2 * ks + 1][3], ph[3]);
                const int kv0 = ks * 16 + l7 + l8;
                uint32_t vh_[4][4], vm_[4][4];
#pragma unroll
                for (int p = 0; p < 4; ++p) {
                    int d0 = p * 16 + l16;
                    ldsm4t(vh_[p], smaddr(&sVh[kv0][d0]));
                    ldsm4t(vm_[p], smaddr(&sVm[kv0][d0]));
                }
#pragma unroll
                for (int p = 0; p < 4; ++p) {
                    mma16(oa[2 * p],     ph, vh_[p]);
                    mma16(oa[2 * p + 1], ph, vh_[p] + 2);
                }
#pragma unroll
                for (int p = 0; p < 4; ++p) {
                    mma16(oa[2 * p],     ph, vm_[p]);
                    mma16(oa[2 * p + 1], ph, vm_[p] + 2);
                }
#pragma unroll
                for (int p = 0; p < 4; ++p) {
                    mma16(oa[2 * p],     pm, vh_[p]);
                    mma16(oa[2 * p + 1], pm, vh_[p] + 2);
                }
            }
            __syncthreads();
        }

        // fold branch into out (RMW; CTA owns its tile across branches)
        float L0 = l0 + __shfl_xor_sync(0xffffffffu, l0, 1);
        L0 += __shfl_xor_sync(0xffffffffu, L0, 2);
        float L1 = l1 + __shfl_xor_sync(0xffffffffu, l1, 1);
        L1 += __shfl_xor_sync(0xffffffffu, L1, 2);
        float i0 = 1.f / L0, i1 = 1.f / L1;
#pragma unroll
        for (int nt = 0; nt < 8; ++nt) {
            int d = nt * 8 + tg * 2;
            size_t base = ((size_t)bb * 1024 + (size_t)(qt * 128 + r0)) * 768 + h * 64 + d;
            float2 v0 = make_float2(oa[nt][0] * i0, oa[nt][1] * i0);
            float2 v1 = make_float2(oa[nt][2] * i1, oa[nt][3] * i1);
            if (brn) {
                float2 o0 = *(float2*)&out[base];
                float2 o1 = *(float2*)&out[base + (size_t)8 * 768];
                v0.x += o0.x; v0.y += o0.y; v1.x += o1.x; v1.y += o1.y;
            }
            *(float2*)&out[base]                   = v0;
            *(float2*)&out[base + (size_t)8 * 768] = v1;
        }
    }
}

// ------------------------------------------------------------------
extern "C" void kernel_launch(void* const* d_in, const int* in_sizes, int n_in,
                              void* d_out, int out_size) {
    (void)in_sizes; (void)n_in; (void)out_size;
    const float* x  = (const float*)d_in[0];
    const float* wq = (const float*)d_in[1];
    const float* bq = (const float*)d_in[2];
    const float* wk = (const float*)d_in[3];
    const float* bk = (const float*)d_in[4];
    const float* wv = (const float*)d_in[5];
    const float* bv = (const float*)d_in[6];
    float* out = (float*)d_out;

    scales_kernel<<<8192, 256>>>(x);
    prep_x<<<dim3(8192, 3), 192>>>(x);
    prep_w<<<dim3(768, 9), 192>>>(wq, wk, wv);

    cudaFuncSetAttribute(proj_mma, cudaFuncAttributeMaxDynamicSharedMemorySize, P_SMEM);
    proj_mma<<<dim3(64, 6, 9), 256, P_SMEM>>>(bq, bk, bv);

    cudaFuncSetAttribute(attn_kernel, cudaFuncAttributeMaxDynamicSharedMemorySize, A_SMEM);
    attn_kernel<<<dim3(8, 12, 8), 256, A_SMEM>>>(out);
}